// round 3
// baseline (speedup 1.0000x reference)
#include <cuda_runtime.h>
#include <math_constants.h>

#define B 8
#define NPTS 4096
#define DIM 64
#define KNB 8
#define NLAYERS 12

// ---------------- device-global scratch (no dynamic allocation allowed) -------------
__device__ float4 g_xyz4[B * NPTS];                 // (x,y,z,|x|^2) per point
__device__ int    g_idx [B * NPTS * KNB];           // knn indices [b][n][k]
__device__ float  g_h   [B * NPTS * DIM];           // normalized features, point-major
__device__ float  g_bufA[B * DIM * NPTS];           // ping
__device__ float  g_bufB[B * DIM * NPTS];           // pong
__device__ float  g_wt  [NLAYERS * DIM * DIM];      // W^T per layer: wt[d][c] = w[c][d]
__device__ float  g_scale[DIM];                     // per-layer BN folded scale
__device__ float  g_shift[DIM];                     // per-layer BN folded shift

// ---------------- prep: pack xyz + squared norm ----------------
__global__ void prep_xyz_kernel(const float* __restrict__ xyz) {
    int i = blockIdx.x * blockDim.x + threadIdx.x;
    if (i >= B * NPTS) return;
    int b = i / NPTS, p = i % NPTS;
    const float* base = xyz + (size_t)b * 3 * NPTS;
    float x = base[p], y = base[NPTS + p], z = base[2 * NPTS + p];
    float sq = x * x + y * y + z * z;
    g_xyz4[i] = make_float4(x, y, z, sq);
}

// ---------------- prep: transpose conv weights ----------------
__global__ void prep_wt_kernel(const float* __restrict__ w) {
    int i = blockIdx.x * blockDim.x + threadIdx.x;
    if (i >= NLAYERS * DIM * DIM) return;
    int l = i / (DIM * DIM), r = i % (DIM * DIM);
    int d = r / DIM, c = r % DIM;
    g_wt[i] = w[l * DIM * DIM + c * DIM + d];
}

// ---------------- KNN: top-8 smallest d2 per query, tie -> lower index ----------------
#define KNN_TPB 128
#define KNN_CHUNK 2048

__global__ void __launch_bounds__(KNN_TPB) knn_kernel() {
    __shared__ float4 cand[KNN_CHUNK];
    int b = blockIdx.y;
    int q = blockIdx.x * KNN_TPB + threadIdx.x;
    const float4* xb = g_xyz4 + b * NPTS;
    float4 me = xb[q];
    float nx = -2.f * me.x, ny = -2.f * me.y, nz = -2.f * me.z;
    float sqi = me.w;

    float bd[KNB];
    int   bi[KNB];
#pragma unroll
    for (int k = 0; k < KNB; k++) { bd[k] = CUDART_INF_F; bi[k] = -1; }

    for (int c0 = 0; c0 < NPTS; c0 += KNN_CHUNK) {
        __syncthreads();
        for (int t = threadIdx.x; t < KNN_CHUNK; t += KNN_TPB) cand[t] = xb[c0 + t];
        __syncthreads();
#pragma unroll 4
        for (int j = 0; j < KNN_CHUNK; j++) {
            float4 cj = cand[j];
            // match reference: sq_i - 2*dot + sq_j (relative order per-row is what matters)
            float d2 = fmaf(cj.x, nx, fmaf(cj.y, ny, fmaf(cj.z, nz, sqi + cj.w)));
            if (d2 < bd[KNB - 1]) {
                bd[KNB - 1] = d2; bi[KNB - 1] = c0 + j;
#pragma unroll
                for (int k = KNB - 1; k >= 1; k--) {
                    if (bd[k] < bd[k - 1]) {   // strict: stable, keeps lower index first on ties
                        float td = bd[k]; bd[k] = bd[k - 1]; bd[k - 1] = td;
                        int   ti = bi[k]; bi[k] = bi[k - 1]; bi[k - 1] = ti;
                    }
                }
            }
        }
    }
    int* orow = g_idx + ((size_t)b * NPTS + q) * KNB;
#pragma unroll
    for (int k = 0; k < KNB; k++) orow[k] = bi[k];
}

// ---------------- per-layer BN stats -> folded scale/shift ----------------
__global__ void stats_kernel(const float* __restrict__ p,
                             const float* __restrict__ gamma,
                             const float* __restrict__ beta) {
    int c = blockIdx.x;
    double s = 0.0, s2 = 0.0;
    for (int b = 0; b < B; b++) {
        const float* row = p + ((size_t)b * DIM + c) * NPTS;
        for (int i = threadIdx.x; i < NPTS; i += blockDim.x) {
            float v = row[i];
            s += v; s2 += (double)v * v;
        }
    }
    __shared__ double ss[256], ss2[256];
    ss[threadIdx.x] = s; ss2[threadIdx.x] = s2;
    __syncthreads();
    for (int o = 128; o > 0; o >>= 1) {
        if (threadIdx.x < o) { ss[threadIdx.x] += ss[threadIdx.x + o]; ss2[threadIdx.x] += ss2[threadIdx.x + o]; }
        __syncthreads();
    }
    if (threadIdx.x == 0) {
        double mean = ss[0] / (double)(B * NPTS);
        double var  = ss2[0] / (double)(B * NPTS) - mean * mean;
        float rstd = rsqrtf((float)var + 1e-5f);
        float sc = gamma[c] * rstd;
        g_scale[c] = sc;
        g_shift[c] = beta[c] - (float)mean * sc;
    }
}

// ---------------- normalize + leaky-relu + transpose to point-major ----------------
__global__ void __launch_bounds__(256) hnorm_kernel(const float* __restrict__ p) {
    __shared__ float tile[DIM][65];
    int b = blockIdx.y;
    int i0 = blockIdx.x * 64;
    int t = threadIdx.x;
#pragma unroll
    for (int k = 0; k < 16; k++) {
        int e = t + k * 256;
        int c = e >> 6, i = e & 63;
        float v = p[((size_t)b * DIM + c) * NPTS + i0 + i];
        v = fmaf(v, g_scale[c], g_shift[c]);
        v = (v >= 0.f) ? v : 0.01f * v;
        tile[c][i] = v;
    }
    __syncthreads();
#pragma unroll
    for (int k = 0; k < 16; k++) {
        int e = t + k * 256;
        int i = e >> 6, c = e & 63;
        g_h[((size_t)b * NPTS + i0 + i) * DIM + c] = tile[c][i];
    }
}

// ---------------- aggregate neighbors + 64x64 matmul + bias + residual ----------------
__global__ void __launch_bounds__(256) block_kernel(const float* __restrict__ pin,
                                                    float* __restrict__ pout,
                                                    const float* __restrict__ wt,
                                                    const float* __restrict__ bias) {
    __shared__ float Wt[DIM][DIM];   // Wt[d][c]
    __shared__ float S[64][66];      // S[i][d], aggregated/(K+1)
    int b = blockIdx.y;
    int i0 = blockIdx.x * 64;
    int t = threadIdx.x;

    // stage W^T
#pragma unroll
    for (int k = 0; k < 16; k++) {
        int e = t + k * 256;
        ((float*)Wt)[e] = wt[e];
    }

    // aggregation: 8 warps x 8 points, each warp sums 9 rows of 64 floats (float2/lane)
    int warp = t >> 5, lane = t & 31;
    const float inv = 1.f / (float)(KNB + 1);
    for (int pp = 0; pp < 8; pp++) {
        int il = warp * 8 + pp;
        int ig = i0 + il;
        const int* irow = g_idx + ((size_t)b * NPTS + ig) * KNB;
        float a0 = 0.f, a1 = 0.f;
#pragma unroll
        for (int k = 0; k <= KNB; k++) {
            int j = (k == 0) ? ig : irow[k - 1];
            const float2* hr = (const float2*)(g_h + ((size_t)b * NPTS + j) * DIM);
            float2 v = hr[lane];
            a0 += v.x; a1 += v.y;
        }
        *(float2*)&S[il][2 * lane] = make_float2(a0 * inv, a1 * inv);
    }
    __syncthreads();

    // matmul: thread handles point i = t%64, channels [c0, c0+16)
    int g  = t >> 6;
    int i  = t & 63;
    int c0 = g * 16;
    float acc[16];
#pragma unroll
    for (int j = 0; j < 16; j++) acc[j] = 0.f;
#pragma unroll 4
    for (int d = 0; d < DIM; d++) {
        float sv = S[i][d];
        const float4* wr = (const float4*)(&Wt[d][c0]);
#pragma unroll
        for (int q = 0; q < 4; q++) {
            float4 w4 = wr[q];
            acc[4 * q + 0] = fmaf(sv, w4.x, acc[4 * q + 0]);
            acc[4 * q + 1] = fmaf(sv, w4.y, acc[4 * q + 1]);
            acc[4 * q + 2] = fmaf(sv, w4.z, acc[4 * q + 2]);
            acc[4 * q + 3] = fmaf(sv, w4.w, acc[4 * q + 3]);
        }
    }
#pragma unroll
    for (int j = 0; j < 16; j++) {
        int c = c0 + j;
        size_t off = ((size_t)b * DIM + c) * NPTS + i0 + i;
        pout[off] = acc[j] + bias[c] + pin[off];
    }
}

// ---------------- launch ----------------
extern "C" void kernel_launch(void* const* d_in, const int* in_sizes, int n_in,
                              void* d_out, int out_size) {
    const float* xyz    = (const float*)d_in[0];
    const float* points = (const float*)d_in[1];
    const float* conv_w = (const float*)d_in[2];
    const float* conv_b = (const float*)d_in[3];
    const float* gamma  = (const float*)d_in[4];
    const float* beta   = (const float*)d_in[5];
    float* out = (float*)d_out;

    float *bufA, *bufB, *wtp;
    cudaGetSymbolAddress((void**)&bufA, g_bufA);
    cudaGetSymbolAddress((void**)&bufB, g_bufB);
    cudaGetSymbolAddress((void**)&wtp,  g_wt);

    prep_xyz_kernel<<<(B * NPTS + 255) / 256, 256>>>(xyz);
    prep_wt_kernel<<<(NLAYERS * DIM * DIM + 255) / 256, 256>>>(conv_w);
    knn_kernel<<<dim3(NPTS / KNN_TPB, B), KNN_TPB>>>();

    const float* cur = points;
    for (int l = 0; l < NLAYERS; l++) {
        float* nxt = (l == NLAYERS - 1) ? out : ((l & 1) ? bufB : bufA);
        stats_kernel<<<DIM, 256>>>(cur, gamma + l * DIM, beta + l * DIM);
        hnorm_kernel<<<dim3(NPTS / 64, B), 256>>>(cur);
        block_kernel<<<dim3(NPTS / 64, B), 256>>>(cur, nxt, wtp + l * DIM * DIM, conv_b + l * DIM);
        cur = nxt;
    }
}

// round 6
// speedup vs baseline: 1.7379x; 1.7379x over previous
#include <cuda_runtime.h>
#include <math_constants.h>

#define B 8
#define NPTS 4096
#define DIM 64
#define KNB 8
#define NLAYERS 12

// ---------------- device-global scratch (no dynamic allocation allowed) -------------
__device__ float4 g_xyz4[B * NPTS];                 // (x,y,z,|x|^2) per point
__device__ int    g_idx [B * NPTS * KNB];           // knn indices [b][n][k]
__device__ float  g_h   [B * NPTS * DIM];           // normalized features, point-major
__device__ float  g_bufA[B * DIM * NPTS];           // ping
__device__ float  g_bufB[B * DIM * NPTS];           // pong
__device__ float  g_wt  [NLAYERS * DIM * DIM];      // W^T per layer: wt[d][c] = w[c][d]
__device__ float  g_scale[DIM];                     // per-layer BN folded scale
__device__ float  g_shift[DIM];                     // per-layer BN folded shift
__device__ double g_acc[2 * DIM];                   // [c]=sum, [DIM+c]=sumsq (next layer)

// ---------------- prep: pack xyz + squared norm ----------------
__global__ void prep_xyz_kernel(const float* __restrict__ xyz) {
    int i = blockIdx.x * blockDim.x + threadIdx.x;
    if (i >= B * NPTS) return;
    int b = i / NPTS, p = i % NPTS;
    const float* base = xyz + (size_t)b * 3 * NPTS;
    float x = base[p], y = base[NPTS + p], z = base[2 * NPTS + p];
    float sq = x * x + y * y + z * z;
    g_xyz4[i] = make_float4(x, y, z, sq);
}

// ---------------- prep: transpose conv weights ----------------
__global__ void prep_wt_kernel(const float* __restrict__ w) {
    int i = blockIdx.x * blockDim.x + threadIdx.x;
    if (i >= NLAYERS * DIM * DIM) return;
    int l = i / (DIM * DIM), r = i % (DIM * DIM);
    int d = r / DIM, c = r % DIM;
    g_wt[i] = w[l * DIM * DIM + c * DIM + d];
}

// ---------------- zero stat accumulators (also resets per graph replay) -------------
__global__ void zero_acc_kernel() {
    int t = threadIdx.x;
    if (t < 2 * DIM) g_acc[t] = 0.0;
}

// ---------------- KNN: top-8 smallest d2 per query, tie -> lower index ----------------
#define KNN_TPB 128
#define KNN_CHUNK 2048

__global__ void __launch_bounds__(KNN_TPB) knn_kernel() {
    __shared__ float4 cand[KNN_CHUNK];
    int b = blockIdx.y;
    int q = blockIdx.x * KNN_TPB + threadIdx.x;
    const float4* xb = g_xyz4 + b * NPTS;
    float4 me = xb[q];
    float nx = -2.f * me.x, ny = -2.f * me.y, nz = -2.f * me.z;
    float sqi = me.w;

    float bd[KNB];
    int   bi[KNB];
#pragma unroll
    for (int k = 0; k < KNB; k++) { bd[k] = CUDART_INF_F; bi[k] = -1; }

    for (int c0 = 0; c0 < NPTS; c0 += KNN_CHUNK) {
        __syncthreads();
        for (int t = threadIdx.x; t < KNN_CHUNK; t += KNN_TPB) cand[t] = xb[c0 + t];
        __syncthreads();
#pragma unroll 4
        for (int j = 0; j < KNN_CHUNK; j++) {
            float4 cj = cand[j];
            float d2 = fmaf(cj.x, nx, fmaf(cj.y, ny, fmaf(cj.z, nz, sqi + cj.w)));
            if (d2 < bd[KNB - 1]) {
                bd[KNB - 1] = d2; bi[KNB - 1] = c0 + j;
#pragma unroll
                for (int k = KNB - 1; k >= 1; k--) {
                    if (bd[k] < bd[k - 1]) {   // strict: stable, keeps lower index first on ties
                        float td = bd[k]; bd[k] = bd[k - 1]; bd[k - 1] = td;
                        int   ti = bi[k]; bi[k] = bi[k - 1]; bi[k - 1] = ti;
                    }
                }
            }
        }
    }
    int* orow = g_idx + ((size_t)b * NPTS + q) * KNB;
#pragma unroll
    for (int k = 0; k < KNB; k++) orow[k] = bi[k];
}

// ---------------- layer-0 stats: fp32 partials -> double atomics ----------------
__global__ void __launch_bounds__(256) stats0_kernel(const float* __restrict__ p) {
    int c = blockIdx.x, b = blockIdx.y;
    const float* row = p + ((size_t)b * DIM + c) * NPTS;
    float s = 0.f, q = 0.f;
    for (int i = threadIdx.x; i < NPTS; i += 256) {
        float v = row[i];
        s += v; q = fmaf(v, v, q);
    }
    __shared__ float ss[256], qq[256];
    ss[threadIdx.x] = s; qq[threadIdx.x] = q;
    __syncthreads();
    for (int o = 128; o > 0; o >>= 1) {
        if (threadIdx.x < o) { ss[threadIdx.x] += ss[threadIdx.x + o]; qq[threadIdx.x] += qq[threadIdx.x + o]; }
        __syncthreads();
    }
    if (threadIdx.x == 0) {
        atomicAdd(&g_acc[c],       (double)ss[0]);
        atomicAdd(&g_acc[DIM + c], (double)qq[0]);
    }
}

// ---------------- finalize: sums -> folded scale/shift, then re-zero ----------------
__global__ void finalize_kernel(const float* __restrict__ gamma,
                                const float* __restrict__ beta) {
    int c = threadIdx.x;
    if (c >= DIM) return;
    double s = g_acc[c], q = g_acc[DIM + c];
    double mean = s / (double)(B * NPTS);
    double var  = q / (double)(B * NPTS) - mean * mean;
    float rstd = rsqrtf((float)var + 1e-5f);
    float sc = gamma[c] * rstd;
    g_scale[c] = sc;
    g_shift[c] = beta[c] - (float)mean * sc;
    g_acc[c] = 0.0; g_acc[DIM + c] = 0.0;
}

// ---------------- normalize + leaky-relu + transpose to point-major ----------------
__global__ void __launch_bounds__(256) hnorm_kernel(const float* __restrict__ p) {
    __shared__ float tile[DIM][65];
    int b = blockIdx.y;
    int i0 = blockIdx.x * 64;
    int t = threadIdx.x;
#pragma unroll
    for (int k = 0; k < 16; k++) {
        int e = t + k * 256;
        int c = e >> 6, i = e & 63;
        float v = p[((size_t)b * DIM + c) * NPTS + i0 + i];
        v = fmaf(v, g_scale[c], g_shift[c]);
        v = (v >= 0.f) ? v : 0.01f * v;
        tile[c][i] = v;
    }
    __syncthreads();
#pragma unroll
    for (int k = 0; k < 16; k++) {
        int e = t + k * 256;
        int i = e >> 6, c = e & 63;
        g_h[((size_t)b * NPTS + i0 + i) * DIM + c] = tile[c][i];
    }
}

// ---- aggregate neighbors + 64x64 matmul + bias + residual + fused next-layer stats ----
__global__ void __launch_bounds__(256) block_kernel(const float* __restrict__ pin,
                                                    float* __restrict__ pout,
                                                    const float* __restrict__ wt,
                                                    const float* __restrict__ bias) {
    __shared__ float Wt[DIM][DIM];   // Wt[d][c]
    __shared__ float S[64][66];      // phase 1: S[i][d] aggregated/(K+1); phase 2: out tile [c][i]
    int b = blockIdx.y;
    int i0 = blockIdx.x * 64;
    int t = threadIdx.x;

    // stage W^T
#pragma unroll
    for (int k = 0; k < 16; k++) {
        int e = t + k * 256;
        ((float*)Wt)[e] = wt[e];
    }

    // aggregation: 8 warps x 8 points, each warp sums 9 rows of 64 floats (float2/lane)
    int warp = t >> 5, lane = t & 31;
    const float inv = 1.f / (float)(KNB + 1);
    for (int pp = 0; pp < 8; pp++) {
        int il = warp * 8 + pp;
        int ig = i0 + il;
        const int* irow = g_idx + ((size_t)b * NPTS + ig) * KNB;
        float a0 = 0.f, a1 = 0.f;
#pragma unroll
        for (int k = 0; k <= KNB; k++) {
            int j = (k == 0) ? ig : irow[k - 1];
            const float2* hr = (const float2*)(g_h + ((size_t)b * NPTS + j) * DIM);
            float2 v = hr[lane];
            a0 += v.x; a1 += v.y;
        }
        *(float2*)&S[il][2 * lane] = make_float2(a0 * inv, a1 * inv);
    }
    __syncthreads();

    // matmul: thread handles point i = t%64, channels [c0, c0+16)
    int g  = t >> 6;
    int i  = t & 63;
    int c0 = g * 16;
    float acc[16];
#pragma unroll
    for (int j = 0; j < 16; j++) acc[j] = 0.f;
#pragma unroll 4
    for (int d = 0; d < DIM; d++) {
        float sv = S[i][d];
        const float4* wr = (const float4*)(&Wt[d][c0]);
#pragma unroll
        for (int q = 0; q < 4; q++) {
            float4 w4 = wr[q];
            acc[4 * q + 0] = fmaf(sv, w4.x, acc[4 * q + 0]);
            acc[4 * q + 1] = fmaf(sv, w4.y, acc[4 * q + 1]);
            acc[4 * q + 2] = fmaf(sv, w4.z, acc[4 * q + 2]);
            acc[4 * q + 3] = fmaf(sv, w4.w, acc[4 * q + 3]);
        }
    }
    // write outputs (bias + residual) and keep values for the stats epilogue
#pragma unroll
    for (int j = 0; j < 16; j++) {
        int c = c0 + j;
        size_t off = ((size_t)b * DIM + c) * NPTS + i0 + i;
        float v = acc[j] + bias[c] + pin[off];
        pout[off] = v;
        acc[j] = v;
    }
    __syncthreads();   // all matmul reads of S complete before reuse
#pragma unroll
    for (int j = 0; j < 16; j++) S[c0 + j][i] = acc[j];
    __syncthreads();

    // per-channel partial sums of this 64-point tile -> global double accumulators
    if (t < DIM) {
        float s0 = 0.f, s1 = 0.f, q0 = 0.f, q1 = 0.f;
#pragma unroll
        for (int i2 = 0; i2 < 64; i2 += 2) {
            float a = S[t][i2], bb = S[t][i2 + 1];
            s0 += a; s1 += bb;
            q0 = fmaf(a, a, q0); q1 = fmaf(bb, bb, q1);
        }
        atomicAdd(&g_acc[t],       (double)(s0 + s1));
        atomicAdd(&g_acc[DIM + t], (double)(q0 + q1));
    }
}

// ---------------- launch ----------------
extern "C" void kernel_launch(void* const* d_in, const int* in_sizes, int n_in,
                              void* d_out, int out_size) {
    const float* xyz    = (const float*)d_in[0];
    const float* points = (const float*)d_in[1];
    const float* conv_w = (const float*)d_in[2];
    const float* conv_b = (const float*)d_in[3];
    const float* gamma  = (const float*)d_in[4];
    const float* beta   = (const float*)d_in[5];
    float* out = (float*)d_out;

    float *bufA, *bufB, *wtp;
    cudaGetSymbolAddress((void**)&bufA, g_bufA);
    cudaGetSymbolAddress((void**)&bufB, g_bufB);
    cudaGetSymbolAddress((void**)&wtp,  g_wt);

    zero_acc_kernel<<<1, 128>>>();
    prep_xyz_kernel<<<(B * NPTS + 255) / 256, 256>>>(xyz);
    prep_wt_kernel<<<(NLAYERS * DIM * DIM + 255) / 256, 256>>>(conv_w);
    knn_kernel<<<dim3(NPTS / KNN_TPB, B), KNN_TPB>>>();
    stats0_kernel<<<dim3(DIM, B), 256>>>(points);

    const float* cur = points;
    for (int l = 0; l < NLAYERS; l++) {
        float* nxt = (l == NLAYERS - 1) ? out : ((l & 1) ? bufB : bufA);
        finalize_kernel<<<1, 64>>>(gamma + l * DIM, beta + l * DIM);
        hnorm_kernel<<<dim3(NPTS / 64, B), 256>>>(cur);
        block_kernel<<<dim3(NPTS / 64, B), 256>>>(cur, nxt, wtp + l * DIM * DIM, conv_b + l * DIM);
        cur = nxt;
    }
}

// round 7
// speedup vs baseline: 1.8444x; 1.0613x over previous
#include <cuda_runtime.h>
#include <math_constants.h>

#define B 8
#define NPTS 4096
#define DIM 64
#define KNB 8
#define NLAYERS 12

#define KNN_SPLIT 2
#define CAND_PER_BLOCK (NPTS / KNN_SPLIT)   // 2048
#define KNN_TPB 128

// ---------------- device-global scratch (no dynamic allocation allowed) -------------
__device__ float4 g_xyz4[B * NPTS];                     // (x,y,z,|x|^2) per point
__device__ int    g_idx [B * NPTS * KNB];               // knn indices [b][n][k]
__device__ float  g_knn_d[B * NPTS * KNN_SPLIT * KNB];  // partial top-8 distances
__device__ int    g_knn_i[B * NPTS * KNN_SPLIT * KNB];  // partial top-8 indices
__device__ float  g_h   [B * NPTS * DIM];               // normalized features, point-major
__device__ float  g_bufA[B * DIM * NPTS];               // ping
__device__ float  g_bufB[B * DIM * NPTS];               // pong
__device__ float  g_wt  [NLAYERS * DIM * DIM];          // W^T per layer: wt[d][c] = w[c][d]
__device__ float  g_scale[DIM];                         // per-layer BN folded scale
__device__ float  g_shift[DIM];                         // per-layer BN folded shift
__device__ double g_acc[2 * DIM];                       // [c]=sum, [DIM+c]=sumsq

// ---------------- prep: pack xyz + squared norm ----------------
__global__ void prep_xyz_kernel(const float* __restrict__ xyz) {
    int i = blockIdx.x * blockDim.x + threadIdx.x;
    if (i >= B * NPTS) return;
    int b = i / NPTS, p = i % NPTS;
    const float* base = xyz + (size_t)b * 3 * NPTS;
    float x = base[p], y = base[NPTS + p], z = base[2 * NPTS + p];
    float sq = x * x + y * y + z * z;
    g_xyz4[i] = make_float4(x, y, z, sq);
}

// ---------------- prep: transpose conv weights ----------------
__global__ void prep_wt_kernel(const float* __restrict__ w) {
    int i = blockIdx.x * blockDim.x + threadIdx.x;
    if (i >= NLAYERS * DIM * DIM) return;
    int l = i / (DIM * DIM), r = i % (DIM * DIM);
    int d = r / DIM, c = r % DIM;
    g_wt[i] = w[l * DIM * DIM + c * DIM + d];
}

// ---------------- zero stat accumulators (also resets per graph replay) -------------
__global__ void zero_acc_kernel() {
    int t = threadIdx.x;
    if (t < 2 * DIM) g_acc[t] = 0.0;
}

// ---------------- KNN pass 1: per-half top-8 (strict stable insertion) ----------------
// Tie behavior: candidates scanned in ascending index; strict '<' bubble keeps
// the earlier (lower-index) entry in front on equal distances.
__global__ void __launch_bounds__(KNN_TPB) knn_kernel() {
    __shared__ float4 cand[CAND_PER_BLOCK];
    int b = blockIdx.y;
    int half = blockIdx.z;
    int q = blockIdx.x * KNN_TPB + threadIdx.x;
    int base = half * CAND_PER_BLOCK;
    const float4* xb = g_xyz4 + b * NPTS;
    float4 me = xb[q];
    float nx = -2.f * me.x, ny = -2.f * me.y, nz = -2.f * me.z;
    float sqi = me.w;

    for (int t = threadIdx.x; t < CAND_PER_BLOCK; t += KNN_TPB) cand[t] = xb[base + t];

    float bd[KNB];
    int   bi[KNB];
#pragma unroll
    for (int k = 0; k < KNB; k++) { bd[k] = CUDART_INF_F; bi[k] = -1; }
    __syncthreads();

#define TRYINS(dv, jv)                                                    \
    if ((dv) < bd[KNB - 1]) {                                             \
        bd[KNB - 1] = (dv); bi[KNB - 1] = (jv);                           \
        _Pragma("unroll")                                                 \
        for (int k = KNB - 1; k >= 1; k--) {                              \
            if (bd[k] < bd[k - 1]) {                                      \
                float td = bd[k]; bd[k] = bd[k - 1]; bd[k - 1] = td;      \
                int   ti = bi[k]; bi[k] = bi[k - 1]; bi[k - 1] = ti;      \
            }                                                             \
        }                                                                 \
    }

    for (int j = 0; j < CAND_PER_BLOCK; j += 4) {
        float4 ca = cand[j], cb = cand[j + 1], cc = cand[j + 2], cd = cand[j + 3];
        float d0 = fmaf(ca.x, nx, fmaf(ca.y, ny, fmaf(ca.z, nz, sqi + ca.w)));
        float d1 = fmaf(cb.x, nx, fmaf(cb.y, ny, fmaf(cb.z, nz, sqi + cb.w)));
        float d2 = fmaf(cc.x, nx, fmaf(cc.y, ny, fmaf(cc.z, nz, sqi + cc.w)));
        float d3 = fmaf(cd.x, nx, fmaf(cd.y, ny, fmaf(cd.z, nz, sqi + cd.w)));
        float m = fminf(fminf(d0, d1), fminf(d2, d3));
        if (m < bd[KNB - 1]) {
            TRYINS(d0, base + j + 0);
            TRYINS(d1, base + j + 1);
            TRYINS(d2, base + j + 2);
            TRYINS(d3, base + j + 3);
        }
    }
#undef TRYINS

    size_t o = ((size_t)(b * NPTS + q) * KNN_SPLIT + half) * KNB;
#pragma unroll
    for (int k = 0; k < KNB; k++) { g_knn_d[o + k] = bd[k]; g_knn_i[o + k] = bi[k]; }
}

// ---------------- KNN pass 2: merge the two sorted top-8 lists ----------------
// Half-0 indices are all < half-1 indices, so 'dA <= dB -> take A' preserves
// lower-index-first on ties (matches reference top_k tie order).
__global__ void knn_merge_kernel() {
    int i = blockIdx.x * blockDim.x + threadIdx.x;
    if (i >= B * NPTS) return;
    size_t o = (size_t)i * KNN_SPLIT * KNB;
    const float* dA = g_knn_d + o;
    const float* dB = dA + KNB;
    const int*   iA = g_knn_i + o;
    const int*   iB = iA + KNB;
    int a = 0, c = 0;
    int* orow = g_idx + (size_t)i * KNB;
#pragma unroll
    for (int k = 0; k < KNB; k++) {
        bool takeA = (c >= KNB) || (a < KNB && dA[a] <= dB[c]);
        orow[k] = takeA ? iA[a] : iB[c];
        if (takeA) a++; else c++;
    }
}

// ---------------- layer-0 stats: fp32 partials -> double atomics ----------------
__global__ void __launch_bounds__(256) stats0_kernel(const float* __restrict__ p) {
    int c = blockIdx.x, b = blockIdx.y;
    const float* row = p + ((size_t)b * DIM + c) * NPTS;
    float s = 0.f, q = 0.f;
    for (int i = threadIdx.x; i < NPTS; i += 256) {
        float v = row[i];
        s += v; q = fmaf(v, v, q);
    }
    __shared__ float ss[256], qq[256];
    ss[threadIdx.x] = s; qq[threadIdx.x] = q;
    __syncthreads();
    for (int o = 128; o > 0; o >>= 1) {
        if (threadIdx.x < o) { ss[threadIdx.x] += ss[threadIdx.x + o]; qq[threadIdx.x] += qq[threadIdx.x + o]; }
        __syncthreads();
    }
    if (threadIdx.x == 0) {
        atomicAdd(&g_acc[c],       (double)ss[0]);
        atomicAdd(&g_acc[DIM + c], (double)qq[0]);
    }
}

// ---------------- finalize: sums -> folded scale/shift, then re-zero ----------------
__global__ void finalize_kernel(const float* __restrict__ gamma,
                                const float* __restrict__ beta) {
    int c = threadIdx.x;
    if (c >= DIM) return;
    double s = g_acc[c], q = g_acc[DIM + c];
    double mean = s / (double)(B * NPTS);
    double var  = q / (double)(B * NPTS) - mean * mean;
    float rstd = rsqrtf((float)var + 1e-5f);
    float sc = gamma[c] * rstd;
    g_scale[c] = sc;
    g_shift[c] = beta[c] - (float)mean * sc;
    g_acc[c] = 0.0; g_acc[DIM + c] = 0.0;
}

// ---------------- normalize + leaky-relu + transpose to point-major ----------------
__global__ void __launch_bounds__(256) hnorm_kernel(const float* __restrict__ p) {
    __shared__ float tile[DIM][65];
    int b = blockIdx.y;
    int i0 = blockIdx.x * 64;
    int t = threadIdx.x;
#pragma unroll
    for (int k = 0; k < 16; k++) {
        int e = t + k * 256;
        int c = e >> 6, i = e & 63;
        float v = p[((size_t)b * DIM + c) * NPTS + i0 + i];
        v = fmaf(v, g_scale[c], g_shift[c]);
        v = (v >= 0.f) ? v : 0.01f * v;
        tile[c][i] = v;
    }
    __syncthreads();
#pragma unroll
    for (int k = 0; k < 16; k++) {
        int e = t + k * 256;
        int i = e >> 6, c = e & 63;
        g_h[((size_t)b * NPTS + i0 + i) * DIM + c] = tile[c][i];
    }
}

// ---- aggregate neighbors + 64x64 matmul + bias + residual + fused next-layer stats ----
__global__ void __launch_bounds__(256) block_kernel(const float* __restrict__ pin,
                                                    float* __restrict__ pout,
                                                    const float* __restrict__ wt,
                                                    const float* __restrict__ bias) {
    __shared__ float Wt[DIM][DIM];   // Wt[d][c]
    __shared__ float S[64][66];      // phase 1: S[i][d] aggregated/(K+1); phase 2: out tile [c][i]
    int b = blockIdx.y;
    int i0 = blockIdx.x * 64;
    int t = threadIdx.x;

    // stage W^T
#pragma unroll
    for (int k = 0; k < 16; k++) {
        int e = t + k * 256;
        ((float*)Wt)[e] = wt[e];
    }

    // aggregation: 8 warps x 8 points, each warp sums 9 rows of 64 floats (float2/lane)
    int warp = t >> 5, lane = t & 31;
    const float inv = 1.f / (float)(KNB + 1);
    for (int pp = 0; pp < 8; pp++) {
        int il = warp * 8 + pp;
        int ig = i0 + il;
        const int* irow = g_idx + ((size_t)b * NPTS + ig) * KNB;
        float a0 = 0.f, a1 = 0.f;
#pragma unroll
        for (int k = 0; k <= KNB; k++) {
            int j = (k == 0) ? ig : irow[k - 1];
            const float2* hr = (const float2*)(g_h + ((size_t)b * NPTS + j) * DIM);
            float2 v = hr[lane];
            a0 += v.x; a1 += v.y;
        }
        *(float2*)&S[il][2 * lane] = make_float2(a0 * inv, a1 * inv);
    }
    __syncthreads();

    // matmul: thread handles point i = t%64, channels [c0, c0+16)
    int g  = t >> 6;
    int i  = t & 63;
    int c0 = g * 16;
    float acc[16];
#pragma unroll
    for (int j = 0; j < 16; j++) acc[j] = 0.f;
#pragma unroll 4
    for (int d = 0; d < DIM; d++) {
        float sv = S[i][d];
        const float4* wr = (const float4*)(&Wt[d][c0]);
#pragma unroll
        for (int q = 0; q < 4; q++) {
            float4 w4 = wr[q];
            acc[4 * q + 0] = fmaf(sv, w4.x, acc[4 * q + 0]);
            acc[4 * q + 1] = fmaf(sv, w4.y, acc[4 * q + 1]);
            acc[4 * q + 2] = fmaf(sv, w4.z, acc[4 * q + 2]);
            acc[4 * q + 3] = fmaf(sv, w4.w, acc[4 * q + 3]);
        }
    }
    // write outputs (bias + residual) and keep values for the stats epilogue
#pragma unroll
    for (int j = 0; j < 16; j++) {
        int c = c0 + j;
        size_t off = ((size_t)b * DIM + c) * NPTS + i0 + i;
        float v = acc[j] + bias[c] + pin[off];
        pout[off] = v;
        acc[j] = v;
    }
    __syncthreads();   // all matmul reads of S complete before reuse
#pragma unroll
    for (int j = 0; j < 16; j++) S[c0 + j][i] = acc[j];
    __syncthreads();

    // per-channel partial sums of this 64-point tile -> global double accumulators
    if (t < DIM) {
        float s0 = 0.f, s1 = 0.f, q0 = 0.f, q1 = 0.f;
#pragma unroll
        for (int i2 = 0; i2 < 64; i2 += 2) {
            float a = S[t][i2], bb = S[t][i2 + 1];
            s0 += a; s1 += bb;
            q0 = fmaf(a, a, q0); q1 = fmaf(bb, bb, q1);
        }
        atomicAdd(&g_acc[t],       (double)(s0 + s1));
        atomicAdd(&g_acc[DIM + t], (double)(q0 + q1));
    }
}

// ---------------- launch ----------------
extern "C" void kernel_launch(void* const* d_in, const int* in_sizes, int n_in,
                              void* d_out, int out_size) {
    const float* xyz    = (const float*)d_in[0];
    const float* points = (const float*)d_in[1];
    const float* conv_w = (const float*)d_in[2];
    const float* conv_b = (const float*)d_in[3];
    const float* gamma  = (const float*)d_in[4];
    const float* beta   = (const float*)d_in[5];
    float* out = (float*)d_out;

    float *bufA, *bufB, *wtp;
    cudaGetSymbolAddress((void**)&bufA, g_bufA);
    cudaGetSymbolAddress((void**)&bufB, g_bufB);
    cudaGetSymbolAddress((void**)&wtp,  g_wt);

    zero_acc_kernel<<<1, 128>>>();
    prep_xyz_kernel<<<(B * NPTS + 255) / 256, 256>>>(xyz);
    prep_wt_kernel<<<(NLAYERS * DIM * DIM + 255) / 256, 256>>>(conv_w);
    knn_kernel<<<dim3(NPTS / KNN_TPB, B, KNN_SPLIT), KNN_TPB>>>();
    knn_merge_kernel<<<(B * NPTS + 255) / 256, 256>>>();
    stats0_kernel<<<dim3(DIM, B), 256>>>(points);

    const float* cur = points;
    for (int l = 0; l < NLAYERS; l++) {
        float* nxt = (l == NLAYERS - 1) ? out : ((l & 1) ? bufB : bufA);
        finalize_kernel<<<1, 64>>>(gamma + l * DIM, beta + l * DIM);
        hnorm_kernel<<<dim3(NPTS / 64, B), 256>>>(cur);
        block_kernel<<<dim3(NPTS / 64, B), 256>>>(cur, nxt, wtp + l * DIM * DIM, conv_b + l * DIM);
        cur = nxt;
    }
}